// round 8
// baseline (speedup 1.0000x reference)
#include <cuda_runtime.h>
#include <cuda_fp16.h>

#define MAXN 100000
#define MAXE 1600000
#define SCAN_B 1024

// Scratch (no allocations allowed — __device__ globals, zero-init at load).
// g_deg/g_cnt/g_scan_ctr are re-zeroed at the END of layer2 so every replay
// starts clean; the first call relies on static zero-init.
__device__ int    g_deg[MAXN];
__device__ int    g_cnt[MAXN];
__device__ int    g_start[MAXN + 1];
__device__ int    g_srcs[MAXE];
__device__ int    g_bsum[128];
__device__ int    g_boff[128];
__device__ int    g_scan_ctr;
__device__ float  g_x1[(size_t)MAXN * 128];          // layer-1 output, fp32
__device__ unsigned g_xh [(size_t)MAXN * 64];        // features as half2 words
__device__ unsigned g_x1h[(size_t)MAXN * 64];        // x1 as half2 words
// Interleaved k-pair weights: g_Wi[t*128 + c] = (W[c][2t], W[c][2t+1])
__device__ float2 g_W1i[8192];
__device__ float2 g_W2i[8192];

__device__ __forceinline__ void fma2(unsigned long long& d,
                                     unsigned long long a,
                                     unsigned long long b) {
    asm("fma.rn.f32x2 %0, %1, %2, %0;" : "+l"(d) : "l"(a), "l"(b));
}

// Launch 0: histogram + weight interleave + fp16 feature shadow
__global__ void k_hist(const int* __restrict__ dst, int E,
                       const float* __restrict__ W1,
                       const float* __restrict__ W2,
                       const float* __restrict__ feat, int N) {
    int i = blockIdx.x * blockDim.x + threadIdx.x;
    if (i < 8192) {
        int t = i >> 7, c = i & 127;
        g_W1i[i] = make_float2(W1[c * 128 + 2 * t], W1[c * 128 + 2 * t + 1]);
        g_W2i[i] = make_float2(W2[c * 128 + 2 * t], W2[c * 128 + 2 * t + 1]);
    }
    int nw = N * 64;
    for (int w = i; w < nw; w += gridDim.x * blockDim.x) {
        float2 f = ((const float2*)feat)[w];
        __half2 h = __float22half2_rn(f);
        g_xh[w] = *(unsigned*)&h;
    }
    if (i < E) atomicAdd(&g_deg[dst[i]], 1);
}

// Launch 1: per-block exclusive scan + block sums; last block scans block sums
__global__ void k_scan1(int N) {
    __shared__ int sh[SCAN_B];
    __shared__ int isLast;
    int i = blockIdx.x * SCAN_B + threadIdx.x;
    int v = (i < N) ? g_deg[i] : 0;
    sh[threadIdx.x] = v;
    __syncthreads();
    for (int off = 1; off < SCAN_B; off <<= 1) {
        int t = (threadIdx.x >= off) ? sh[threadIdx.x - off] : 0;
        __syncthreads();
        sh[threadIdx.x] += t;
        __syncthreads();
    }
    if (i < N) g_start[i] = sh[threadIdx.x] - v;   // exclusive, block-partial
    if (threadIdx.x == SCAN_B - 1) g_bsum[blockIdx.x] = sh[SCAN_B - 1];
    __threadfence();
    __syncthreads();
    if (threadIdx.x == 0)
        isLast = (atomicAdd(&g_scan_ctr, 1) == (int)gridDim.x - 1);
    __syncthreads();
    if (isLast && threadIdx.x == 0) {
        int run = 0;
        for (int k = 0; k < (int)gridDim.x; k++) {
            int t = g_bsum[k]; g_boff[k] = run; run += t;
        }
        __threadfence();
    }
}

// Launch 2: scatter src ids into CSR (lazy block offsets + separate counter)
__global__ void k_scatter(const int* __restrict__ src,
                          const int* __restrict__ dst, int E) {
    int i = blockIdx.x * blockDim.x + threadIdx.x;
    if (i < E) {
        int d = dst[i];
        int pos = g_start[d] + g_boff[d >> 10] + atomicAdd(&g_cnt[d], 1);
        g_srcs[pos] = src[i];
    }
}

// Launches 3/4: fused layer. Warp tile = 8 nodes.
// Gather: fp16 neighbor rows (LDG.64/lane), fp32 accumulate; self term fp32.
// GEMM: packed fma.rn.f32x2, even/odd-k in the two lanes, conflict-free LDS.
// ALL internal buffers resolved in device code from the layer flag.
__global__ void __launch_bounds__(256, 2) k_layer(
        const float* __restrict__ feat_ext,
        float* __restrict__ out_ext,
        const float* __restrict__ b,
        int N, int E, int layer) {
    extern __shared__ float smem[];
    unsigned long long* Wsh = (unsigned long long*)smem;  // 64 KB
    float* srows = smem + 16384;                          // 32 KB

    const float*    self_in = (layer == 1) ? feat_ext : (const float*)g_x1;
    const unsigned* xh      = (layer == 1) ? (const unsigned*)g_xh
                                           : (const unsigned*)g_x1h;
    float*          out     = (layer == 1) ? (float*)g_x1 : out_ext;
    const float2*   Wi      = (layer == 1) ? g_W1i : g_W2i;

    for (int i = threadIdx.x; i < 8192; i += 256)
        ((float2*)Wsh)[i] = Wi[i];
    __syncthreads();

    int w = threadIdx.x >> 5, lane = threadIdx.x & 31;

    // bias for owned cols {2L, 2L+1, 64+2L, 64+2L+1}, packed (bias, 0)
    float2 blo = __ldg((const float2*)b + lane);
    float2 bhi = __ldg((const float2*)b + 32 + lane);
    unsigned long long binit[4];
    binit[0] = (unsigned long long)__float_as_uint(blo.x);
    binit[1] = (unsigned long long)__float_as_uint(blo.y);
    binit[2] = (unsigned long long)__float_as_uint(bhi.x);
    binit[3] = (unsigned long long)__float_as_uint(bhi.y);

    float* myrows = srows + w * (8 * 128);

    int warpId = blockIdx.x * 8 + w;
    int nWarps = gridDim.x * 8;
    int nTiles = (N + 7) >> 3;

    for (int t = warpId; t < nTiles; t += nWarps) {
        int n0 = t << 3;
        int nrows = min(8, N - n0);

        // ---- gather (fp16 neighbors, fp32 accumulate) ----
        for (int r = 0; r < nrows; r++) {
            int n = n0 + r;
            int beg = g_start[n] + g_boff[n >> 10];
            int end = (n + 1 < N) ? g_start[n + 1] + g_boff[(n + 1) >> 10] : E;
            float4 a0 = make_float4(0.f, 0.f, 0.f, 0.f);
            float4 a1 = make_float4(0.f, 0.f, 0.f, 0.f);
            float4 a2 = make_float4(0.f, 0.f, 0.f, 0.f);
            float4 a3 = make_float4(0.f, 0.f, 0.f, 0.f);
            for (int base = beg; base < end; base += 32) {
                int rem = end - base;
                int m = rem < 32 ? rem : 32;
                int idx = (lane < m) ? g_srcs[base + lane] : 0;
                int j = 0;
                for (; j + 3 < m; j += 4) {
                    int s0 = __shfl_sync(0xffffffffu, idx, j);
                    int s1 = __shfl_sync(0xffffffffu, idx, j + 1);
                    int s2 = __shfl_sync(0xffffffffu, idx, j + 2);
                    int s3 = __shfl_sync(0xffffffffu, idx, j + 3);
                    uint2 u0 = *((const uint2*)(xh + (size_t)s0 * 64) + lane);
                    uint2 u1 = *((const uint2*)(xh + (size_t)s1 * 64) + lane);
                    uint2 u2 = *((const uint2*)(xh + (size_t)s2 * 64) + lane);
                    uint2 u3 = *((const uint2*)(xh + (size_t)s3 * 64) + lane);
                    float2 p, q;
                    p = __half22float2(*(__half2*)&u0.x); q = __half22float2(*(__half2*)&u0.y);
                    a0.x += p.x; a0.y += p.y; a0.z += q.x; a0.w += q.y;
                    p = __half22float2(*(__half2*)&u1.x); q = __half22float2(*(__half2*)&u1.y);
                    a1.x += p.x; a1.y += p.y; a1.z += q.x; a1.w += q.y;
                    p = __half22float2(*(__half2*)&u2.x); q = __half22float2(*(__half2*)&u2.y);
                    a2.x += p.x; a2.y += p.y; a2.z += q.x; a2.w += q.y;
                    p = __half22float2(*(__half2*)&u3.x); q = __half22float2(*(__half2*)&u3.y);
                    a3.x += p.x; a3.y += p.y; a3.z += q.x; a3.w += q.y;
                }
                for (; j < m; j++) {
                    int s0 = __shfl_sync(0xffffffffu, idx, j);
                    uint2 u0 = *((const uint2*)(xh + (size_t)s0 * 64) + lane);
                    float2 p = __half22float2(*(__half2*)&u0.x);
                    float2 q = __half22float2(*(__half2*)&u0.y);
                    a0.x += p.x; a0.y += p.y; a0.z += q.x; a0.w += q.y;
                }
            }
            float inv = 1.0f / fmaxf((float)(end - beg), 1.0f);
            float4 f = *((const float4*)(self_in + (size_t)n * 128) + lane);
            float4 comb;
            comb.x = f.x + (a0.x + a1.x + a2.x + a3.x) * inv;
            comb.y = f.y + (a0.y + a1.y + a2.y + a3.y) * inv;
            comb.z = f.z + (a0.z + a1.z + a2.z + a3.z) * inv;
            comb.w = f.w + (a0.w + a1.w + a2.w + a3.w) * inv;
            *(float4*)&myrows[r * 128 + (lane << 2)] = comb;
        }
        __syncwarp();

        // ---- GEMM: 8 rows x 4 cols per lane, packed f32x2 even/odd-k ----
        unsigned long long acc[8][4];
#pragma unroll
        for (int r = 0; r < 8; r++) {
            acc[r][0] = binit[0]; acc[r][1] = binit[1];
            acc[r][2] = binit[2]; acc[r][3] = binit[3];
        }

#pragma unroll 4
        for (int t2 = 0; t2 < 64; t2 += 2) {
            ulonglong2 wAlo = *(const ulonglong2*)(Wsh + (size_t)t2 * 128 + (lane << 1));
            ulonglong2 wAhi = *(const ulonglong2*)(Wsh + (size_t)t2 * 128 + 64 + (lane << 1));
            ulonglong2 wBlo = *(const ulonglong2*)(Wsh + (size_t)(t2 + 1) * 128 + (lane << 1));
            ulonglong2 wBhi = *(const ulonglong2*)(Wsh + (size_t)(t2 + 1) * 128 + 64 + (lane << 1));
#pragma unroll
            for (int r = 0; r < 8; r++) {
                ulonglong2 av = *(const ulonglong2*)&myrows[r * 128 + (t2 << 1)];
                fma2(acc[r][0], av.x, wAlo.x);
                fma2(acc[r][1], av.x, wAlo.y);
                fma2(acc[r][2], av.x, wAhi.x);
                fma2(acc[r][3], av.x, wAhi.y);
                fma2(acc[r][0], av.y, wBlo.x);
                fma2(acc[r][1], av.y, wBlo.y);
                fma2(acc[r][2], av.y, wBhi.x);
                fma2(acc[r][3], av.y, wBhi.y);
            }
        }

        for (int r = 0; r < nrows; r++) {
            float2 olo, ohi;
            olo.x = __uint_as_float((unsigned)acc[r][0]) + __uint_as_float((unsigned)(acc[r][0] >> 32));
            olo.y = __uint_as_float((unsigned)acc[r][1]) + __uint_as_float((unsigned)(acc[r][1] >> 32));
            ohi.x = __uint_as_float((unsigned)acc[r][2]) + __uint_as_float((unsigned)(acc[r][2] >> 32));
            ohi.y = __uint_as_float((unsigned)acc[r][3]) + __uint_as_float((unsigned)(acc[r][3] >> 32));
            if (layer == 1) {
                olo.x = fmaxf(olo.x, 0.f); olo.y = fmaxf(olo.y, 0.f);
                ohi.x = fmaxf(ohi.x, 0.f); ohi.y = fmaxf(ohi.y, 0.f);
                // fp16 shadow for layer-2 gather
                __half2 hlo = __float22half2_rn(olo);
                __half2 hhi = __float22half2_rn(ohi);
                unsigned* hrow = g_x1h + (size_t)(n0 + r) * 64;
                hrow[lane]      = *(unsigned*)&hlo;
                hrow[32 + lane] = *(unsigned*)&hhi;
            }
            float* orow = out + (size_t)(n0 + r) * 128;
            *((float2*)orow + lane)      = olo;
            *((float2*)orow + 32 + lane) = ohi;
        }
        __syncwarp();
    }

    // layer 2 tail: re-zero scratch for the next replay.
    if (layer == 2) {
        int gi = blockIdx.x * blockDim.x + threadIdx.x;
        int gs = gridDim.x * blockDim.x;
        for (int i = gi; i < N; i += gs) { g_deg[i] = 0; g_cnt[i] = 0; }
        if (gi == 0) g_scan_ctr = 0;
    }
}

extern "C" void kernel_launch(void* const* d_in, const int* in_sizes, int n_in,
                              void* d_out, int out_size) {
    const float* feat = (const float*)d_in[0];
    const int*   src  = (const int*)d_in[1];
    const int*   dst  = (const int*)d_in[2];
    const float* W1   = (const float*)d_in[3];
    const float* b1   = (const float*)d_in[4];
    const float* W2   = (const float*)d_in[5];
    const float* b2   = (const float*)d_in[6];
    float* out = (float*)d_out;

    int N = in_sizes[0] / 128;
    int E = in_sizes[1];
    int nb = (N + SCAN_B - 1) / SCAN_B;

    size_t smem = (size_t)(64 * 1024 + 32 * 1024);
    cudaFuncSetAttribute((const void*)k_layer,
                         cudaFuncAttributeMaxDynamicSharedMemorySize, (int)smem);

    k_hist<<<(E + 255) / 256, 256>>>(dst, E, W1, W2, feat, N);       // my #0
    k_scan1<<<nb, SCAN_B>>>(N);                                      // my #1
    k_scatter<<<(E + 255) / 256, 256>>>(src, dst, E);                // my #2
    k_layer<<<296, 256, smem>>>(feat, nullptr, b1, N, E, 1);         // my #3 (global #5 -> profiled)
    k_layer<<<296, 256, smem>>>(nullptr, out, b2, N, E, 2);          // my #4
}

// round 9
// speedup vs baseline: 1.1634x; 1.1634x over previous
#include <cuda_runtime.h>
#include <cuda_fp16.h>

#define MAXN 100000
#define MAXE 1600000
#define SCAN_B 1024

// Scratch (no allocations allowed — __device__ globals, zero-init at load).
// g_deg/g_cnt/g_scan_ctr are re-zeroed at the END of the last kernel so every
// replay starts clean; the first call relies on static zero-init.
__device__ int    g_deg[MAXN];
__device__ int    g_cnt[MAXN];
__device__ int    g_start[MAXN + 1];
__device__ int    g_srcs[MAXE];
__device__ int    g_bsum[128];
__device__ int    g_boff[128];
__device__ int    g_scan_ctr;
__device__ float  g_x1[(size_t)MAXN * 128];          // layer-1 output, fp32
__device__ float  g_comb[(size_t)MAXN * 128];        // gather output (GEMM input)
__device__ unsigned g_xh [(size_t)MAXN * 64];        // features as half2 words
__device__ unsigned g_x1h[(size_t)MAXN * 64];        // x1 as half2 words
// Interleaved k-pair weights: g_Wi[t*128 + c] = (W[c][2t], W[c][2t+1])
__device__ float2 g_W1i[8192];
__device__ float2 g_W2i[8192];

__device__ __forceinline__ void fma2(unsigned long long& d,
                                     unsigned long long a,
                                     unsigned long long b) {
    asm("fma.rn.f32x2 %0, %1, %2, %0;" : "+l"(d) : "l"(a), "l"(b));
}

// Launch 0: histogram + weight interleave + fp16 feature shadow
__global__ void k_hist(const int* __restrict__ dst, int E,
                       const float* __restrict__ W1,
                       const float* __restrict__ W2,
                       const float* __restrict__ feat, int N) {
    int i = blockIdx.x * blockDim.x + threadIdx.x;
    if (i < 8192) {
        int t = i >> 7, c = i & 127;
        g_W1i[i] = make_float2(W1[c * 128 + 2 * t], W1[c * 128 + 2 * t + 1]);
        g_W2i[i] = make_float2(W2[c * 128 + 2 * t], W2[c * 128 + 2 * t + 1]);
    }
    int nw = N * 64;
    for (int w = i; w < nw; w += gridDim.x * blockDim.x) {
        float2 f = ((const float2*)feat)[w];
        __half2 h = __float22half2_rn(f);
        g_xh[w] = *(unsigned*)&h;
    }
    if (i < E) atomicAdd(&g_deg[dst[i]], 1);
}

// Launch 1: per-block exclusive scan + block sums; last block scans block sums
__global__ void k_scan1(int N) {
    __shared__ int sh[SCAN_B];
    __shared__ int isLast;
    int i = blockIdx.x * SCAN_B + threadIdx.x;
    int v = (i < N) ? g_deg[i] : 0;
    sh[threadIdx.x] = v;
    __syncthreads();
    for (int off = 1; off < SCAN_B; off <<= 1) {
        int t = (threadIdx.x >= off) ? sh[threadIdx.x - off] : 0;
        __syncthreads();
        sh[threadIdx.x] += t;
        __syncthreads();
    }
    if (i < N) g_start[i] = sh[threadIdx.x] - v;   // exclusive, block-partial
    if (threadIdx.x == SCAN_B - 1) g_bsum[blockIdx.x] = sh[SCAN_B - 1];
    __threadfence();
    __syncthreads();
    if (threadIdx.x == 0)
        isLast = (atomicAdd(&g_scan_ctr, 1) == (int)gridDim.x - 1);
    __syncthreads();
    if (isLast && threadIdx.x == 0) {
        int run = 0;
        for (int k = 0; k < (int)gridDim.x; k++) {
            int t = g_bsum[k]; g_boff[k] = run; run += t;
        }
        __threadfence();
    }
}

// Launch 2: scatter src ids into CSR (lazy block offsets + separate counter)
__global__ void k_scatter(const int* __restrict__ src,
                          const int* __restrict__ dst, int E) {
    int i = blockIdx.x * blockDim.x + threadIdx.x;
    if (i < E) {
        int d = dst[i];
        int pos = g_start[d] + g_boff[d >> 10] + atomicAdd(&g_cnt[d], 1);
        g_srcs[pos] = src[i];
    }
}

// Gather-only kernel: warp per node, zero smem, low regs -> high occupancy.
// comb = self(fp32) + mean(neighbors from fp16 shadow). Writes g_comb.
__global__ void __launch_bounds__(256) k_gather(
        const float* __restrict__ feat_ext, int N, int E, int layer) {
    const float*    self_in = (layer == 1) ? feat_ext : (const float*)g_x1;
    const unsigned* xh      = (layer == 1) ? (const unsigned*)g_xh
                                           : (const unsigned*)g_x1h;

    int w = threadIdx.x >> 5, lane = threadIdx.x & 31;
    int n = blockIdx.x * 8 + w;
    if (n >= N) return;

    int beg = g_start[n] + g_boff[n >> 10];
    int end = (n + 1 < N) ? g_start[n + 1] + g_boff[(n + 1) >> 10] : E;

    float4 a0 = make_float4(0.f, 0.f, 0.f, 0.f);
    float4 a1 = make_float4(0.f, 0.f, 0.f, 0.f);
    float4 a2 = make_float4(0.f, 0.f, 0.f, 0.f);
    float4 a3 = make_float4(0.f, 0.f, 0.f, 0.f);
    for (int base = beg; base < end; base += 32) {
        int rem = end - base;
        int m = rem < 32 ? rem : 32;
        int idx = (lane < m) ? g_srcs[base + lane] : 0;
        int j = 0;
        for (; j + 3 < m; j += 4) {
            int s0 = __shfl_sync(0xffffffffu, idx, j);
            int s1 = __shfl_sync(0xffffffffu, idx, j + 1);
            int s2 = __shfl_sync(0xffffffffu, idx, j + 2);
            int s3 = __shfl_sync(0xffffffffu, idx, j + 3);
            uint2 u0 = *((const uint2*)(xh + (size_t)s0 * 64) + lane);
            uint2 u1 = *((const uint2*)(xh + (size_t)s1 * 64) + lane);
            uint2 u2 = *((const uint2*)(xh + (size_t)s2 * 64) + lane);
            uint2 u3 = *((const uint2*)(xh + (size_t)s3 * 64) + lane);
            float2 p, q;
            p = __half22float2(*(__half2*)&u0.x); q = __half22float2(*(__half2*)&u0.y);
            a0.x += p.x; a0.y += p.y; a0.z += q.x; a0.w += q.y;
            p = __half22float2(*(__half2*)&u1.x); q = __half22float2(*(__half2*)&u1.y);
            a1.x += p.x; a1.y += p.y; a1.z += q.x; a1.w += q.y;
            p = __half22float2(*(__half2*)&u2.x); q = __half22float2(*(__half2*)&u2.y);
            a2.x += p.x; a2.y += p.y; a2.z += q.x; a2.w += q.y;
            p = __half22float2(*(__half2*)&u3.x); q = __half22float2(*(__half2*)&u3.y);
            a3.x += p.x; a3.y += p.y; a3.z += q.x; a3.w += q.y;
        }
        for (; j < m; j++) {
            int s0 = __shfl_sync(0xffffffffu, idx, j);
            uint2 u0 = *((const uint2*)(xh + (size_t)s0 * 64) + lane);
            float2 p = __half22float2(*(__half2*)&u0.x);
            float2 q = __half22float2(*(__half2*)&u0.y);
            a0.x += p.x; a0.y += p.y; a0.z += q.x; a0.w += q.y;
        }
    }
    float inv = 1.0f / fmaxf((float)(end - beg), 1.0f);
    float4 f = *((const float4*)(self_in + (size_t)n * 128) + lane);
    float4 comb;
    comb.x = f.x + (a0.x + a1.x + a2.x + a3.x) * inv;
    comb.y = f.y + (a0.y + a1.y + a2.y + a3.y) * inv;
    comb.z = f.z + (a0.z + a1.z + a2.z + a3.z) * inv;
    comb.w = f.w + (a0.w + a1.w + a2.w + a3.w) * inv;
    *((float4*)(g_comb + (size_t)n * 128) + lane) = comb;
}

// GEMM-only kernel: warp tile = 8 rows from g_comb (coalesced stage to smem),
// packed fma.rn.f32x2, even/odd-k in the two lanes, conflict-free W LDS.
__global__ void __launch_bounds__(256, 2) k_gemm(
        float* __restrict__ out_ext,
        const float* __restrict__ b,
        int N, int layer) {
    extern __shared__ float smem[];
    unsigned long long* Wsh = (unsigned long long*)smem;  // 64 KB
    float* srows = smem + 16384;                          // 32 KB

    float*        out = (layer == 1) ? (float*)g_x1 : out_ext;
    const float2* Wi  = (layer == 1) ? g_W1i : g_W2i;

    for (int i = threadIdx.x; i < 8192; i += 256)
        ((float2*)Wsh)[i] = Wi[i];
    __syncthreads();

    int w = threadIdx.x >> 5, lane = threadIdx.x & 31;

    float2 blo = __ldg((const float2*)b + lane);
    float2 bhi = __ldg((const float2*)b + 32 + lane);
    unsigned long long binit[4];
    binit[0] = (unsigned long long)__float_as_uint(blo.x);
    binit[1] = (unsigned long long)__float_as_uint(blo.y);
    binit[2] = (unsigned long long)__float_as_uint(bhi.x);
    binit[3] = (unsigned long long)__float_as_uint(bhi.y);

    float* myrows = srows + w * (8 * 128);

    int warpId = blockIdx.x * 8 + w;
    int nWarps = gridDim.x * 8;
    int nTiles = (N + 7) >> 3;

    for (int t = warpId; t < nTiles; t += nWarps) {
        int n0 = t << 3;
        int nrows = min(8, N - n0);

        // stage 8 rows (coalesced LDG.128)
#pragma unroll
        for (int r = 0; r < 8; r++) {
            if (r < nrows) {
                float4 v = *((const float4*)(g_comb + (size_t)(n0 + r) * 128) + lane);
                *(float4*)&myrows[r * 128 + (lane << 2)] = v;
            }
        }
        __syncwarp();

        unsigned long long acc[8][4];
#pragma unroll
        for (int r = 0; r < 8; r++) {
            acc[r][0] = binit[0]; acc[r][1] = binit[1];
            acc[r][2] = binit[2]; acc[r][3] = binit[3];
        }

#pragma unroll 4
        for (int t2 = 0; t2 < 64; t2 += 2) {
            ulonglong2 wAlo = *(const ulonglong2*)(Wsh + (size_t)t2 * 128 + (lane << 1));
            ulonglong2 wAhi = *(const ulonglong2*)(Wsh + (size_t)t2 * 128 + 64 + (lane << 1));
            ulonglong2 wBlo = *(const ulonglong2*)(Wsh + (size_t)(t2 + 1) * 128 + (lane << 1));
            ulonglong2 wBhi = *(const ulonglong2*)(Wsh + (size_t)(t2 + 1) * 128 + 64 + (lane << 1));
#pragma unroll
            for (int r = 0; r < 8; r++) {
                ulonglong2 av = *(const ulonglong2*)&myrows[r * 128 + (t2 << 1)];
                fma2(acc[r][0], av.x, wAlo.x);
                fma2(acc[r][1], av.x, wAlo.y);
                fma2(acc[r][2], av.x, wAhi.x);
                fma2(acc[r][3], av.x, wAhi.y);
                fma2(acc[r][0], av.y, wBlo.x);
                fma2(acc[r][1], av.y, wBlo.y);
                fma2(acc[r][2], av.y, wBhi.x);
                fma2(acc[r][3], av.y, wBhi.y);
            }
        }

        for (int r = 0; r < nrows; r++) {
            float2 olo, ohi;
            olo.x = __uint_as_float((unsigned)acc[r][0]) + __uint_as_float((unsigned)(acc[r][0] >> 32));
            olo.y = __uint_as_float((unsigned)acc[r][1]) + __uint_as_float((unsigned)(acc[r][1] >> 32));
            ohi.x = __uint_as_float((unsigned)acc[r][2]) + __uint_as_float((unsigned)(acc[r][2] >> 32));
            ohi.y = __uint_as_float((unsigned)acc[r][3]) + __uint_as_float((unsigned)(acc[r][3] >> 32));
            if (layer == 1) {
                olo.x = fmaxf(olo.x, 0.f); olo.y = fmaxf(olo.y, 0.f);
                ohi.x = fmaxf(ohi.x, 0.f); ohi.y = fmaxf(ohi.y, 0.f);
                __half2 hlo = __float22half2_rn(olo);
                __half2 hhi = __float22half2_rn(ohi);
                unsigned* hrow = g_x1h + (size_t)(n0 + r) * 64;
                hrow[lane]      = *(unsigned*)&hlo;
                hrow[32 + lane] = *(unsigned*)&hhi;
            }
            float* orow = out + (size_t)(n0 + r) * 128;
            *((float2*)orow + lane)      = olo;
            *((float2*)orow + 32 + lane) = ohi;
        }
        __syncwarp();
    }

    // layer 2 tail: re-zero scratch for the next replay.
    if (layer == 2) {
        int gi = blockIdx.x * blockDim.x + threadIdx.x;
        int gs = gridDim.x * blockDim.x;
        for (int i = gi; i < N; i += gs) { g_deg[i] = 0; g_cnt[i] = 0; }
        if (gi == 0) g_scan_ctr = 0;
    }
}

extern "C" void kernel_launch(void* const* d_in, const int* in_sizes, int n_in,
                              void* d_out, int out_size) {
    const float* feat = (const float*)d_in[0];
    const int*   src  = (const int*)d_in[1];
    const int*   dst  = (const int*)d_in[2];
    const float* W1   = (const float*)d_in[3];
    const float* b1   = (const float*)d_in[4];
    const float* W2   = (const float*)d_in[5];
    const float* b2   = (const float*)d_in[6];
    float* out = (float*)d_out;

    int N = in_sizes[0] / 128;
    int E = in_sizes[1];
    int nb = (N + SCAN_B - 1) / SCAN_B;
    int gblocks = (N + 7) / 8;

    size_t smem = (size_t)(64 * 1024 + 32 * 1024);
    cudaFuncSetAttribute((const void*)k_gemm,
                         cudaFuncAttributeMaxDynamicSharedMemorySize, (int)smem);

    k_hist<<<(E + 255) / 256, 256>>>(dst, E, W1, W2, feat, N);   // my #0
    k_scan1<<<nb, SCAN_B>>>(N);                                  // my #1
    k_scatter<<<(E + 255) / 256, 256>>>(src, dst, E);            // my #2
    k_gather<<<gblocks, 256>>>(feat, N, E, 1);                   // my #3 (global #5 -> profiled)
    k_gemm<<<296, 256, smem>>>(nullptr, b1, N, 1);               // my #4
    k_gather<<<gblocks, 256>>>(nullptr, N, E, 2);                // my #5
    k_gemm<<<296, 256, smem>>>(out, b2, N, 2);                   // my #6
}